// round 13
// baseline (speedup 1.0000x reference)
#include <cuda_runtime.h>
#include <cstdint>

// ---------------------------------------------------------------------------
// PoincareEmbeddings: out[b,l,:] = custom ? T[cm] : Rw[rm] + lin_b
// where T[k] = lin_w @ mobius_add(logmap0(fixed[k]), train[k]) + lin_b
//
// R13 = R12 kernels + stream overlap enabled by token COMPACTION:
//   side: mobius -> wprep -> gemm              (builds g_T; DRAM-light)
//   main: zero -> compact -> gather_regular    (80% of rows; DRAM-bound)
//   join: gather_custom                        (rows from g_T, L2-resident)
// Compaction stores (tok, table-row) pairs, eliminating g_ptr and double scans.
// List order from atomics is nondeterministic but the OUTPUT is order-independent.
// ---------------------------------------------------------------------------

constexpr int P_    = 300;
constexpr int PPAD  = 320;
constexpr int E_    = 256;
constexpr int Kc    = 20000;
constexpr int KP1   = Kc + 1;
constexpr int KROWS = 20096;      // 314 * 64 == 1256 * 16
constexpr int NBT   = KROWS / 64; // 314 GEMM row-tiles
constexpr int NMB   = KROWS / 16; // 1256 mobius blocks
constexpr int NTOKMAX = 262144;   // B*L

__device__ float g_Mp[(size_t)KROWS * PPAD];  // fragment-permuted mobius output
__device__ float g_T[(size_t)KROWS * E_];     // projected custom embeddings (+bias)
__device__ float g_Wp[(size_t)E_ * PPAD];     // lin_w, tf32, fragment-permuted
__device__ int  g_cnt[2];                     // [0]=custom count, [1]=regular count
__device__ int2 g_lcus[NTOKMAX];              // (tok, cm)
__device__ int2 g_lreg[NTOKMAX];              // (tok, rm)

__device__ __forceinline__ float tf32_rna(float x) {
    float r;
    asm("cvt.rna.tf32.f32 %0, %1;" : "=f"(r) : "f"(x));
    return r;
}

// ---------------------------------------------------------------------------
// Prep A: lin_w -> g_Wp fragment-permuted tf32 (validated R7-R12).
// ---------------------------------------------------------------------------
__global__ void __launch_bounds__(256) k_wprep(const float* __restrict__ W) {
    int idx = blockIdx.x * 256 + threadIdx.x;
    if (idx >= E_ * PPAD) return;
    int slot = idx & 1;
    int lane = (idx >> 1) & 31;
    int t_n  = (idx >> 6) & 31;
    int t_k  = idx >> 11;
    int n = t_n * 8 + (lane >> 2);
    int k = t_k * 8 + (lane & 3) + slot * 4;
    g_Wp[idx] = (k < P_) ? tf32_rna(__ldg(W + (size_t)n * P_ + k)) : 0.f;
}

// ---------------------------------------------------------------------------
// Counter reset (graph-replayed every launch)
// ---------------------------------------------------------------------------
__global__ void k_zero() {
    if (threadIdx.x < 2) g_cnt[threadIdx.x] = 0;
}

// ---------------------------------------------------------------------------
// Compaction: partition tokens into custom/regular lists with per-warp
// ballot aggregation (2 atomics per warp). Output order-independent.
// ---------------------------------------------------------------------------
__global__ void __launch_bounds__(256) k_compact(const int* __restrict__ x,
                                                 const int* __restrict__ v2c,
                                                 const int* __restrict__ v2r,
                                                 int ntok) {
    int tok  = blockIdx.x * 256 + threadIdx.x;
    int lane = threadIdx.x & 31;
    bool valid = tok < ntok;
    int v  = valid ? __ldg(x + tok) : 0;
    int cm = valid ? __ldg(v2c + v) : 0;
    bool cus = valid && (cm != 0);
    bool reg = valid && (cm == 0);
    int rm = reg ? __ldg(v2r + v) : 0;

    unsigned mc = __ballot_sync(0xFFFFFFFFu, cus);
    unsigned mr = __ballot_sync(0xFFFFFFFFu, reg);
    int basec = 0, baser = 0;
    if (lane == 0) {
        if (mc) basec = atomicAdd(&g_cnt[0], __popc(mc));
        if (mr) baser = atomicAdd(&g_cnt[1], __popc(mr));
    }
    basec = __shfl_sync(0xFFFFFFFFu, basec, 0);
    baser = __shfl_sync(0xFFFFFFFFu, baser, 0);
    unsigned below = (1u << lane) - 1u;
    if (cus) g_lcus[basec + __popc(mc & below)] = make_int2(tok, cm);
    if (reg) g_lreg[baser + __popc(mr & below)] = make_int2(tok, rm);
}

// ---------------------------------------------------------------------------
// Kernel 1: mobius -> fragment-permuted A (EXACT R12, measured ~14.5us).
// ---------------------------------------------------------------------------
constexpr int MST = 324;

__global__ void __launch_bounds__(256) k_mobius(const float* __restrict__ fixed_w,
                                                const float* __restrict__ train_w) {
    __shared__ float stage[16 * MST];

    int tid  = threadIdx.x;
    int warp = tid >> 5;
    int lane = tid & 31;
    int mb   = blockIdx.x;
    int rowBase = mb * 16;

#pragma unroll
    for (int r2 = 0; r2 < 2; r2++) {
        int row = warp * 2 + r2;
        int gr  = rowBase + row;
        int rs  = (gr < KP1) ? gr : 0;
        const float* f = fixed_w + (size_t)rs * P_;
        const float* t = train_w + (size_t)rs * P_;

        float fr[10], tr[10];
        float sf2 = 0.f, sft = 0.f, st2 = 0.f;
#pragma unroll
        for (int i = 0; i < 10; i++) {
            int p = lane + i * 32;
            float fv = (p < P_) ? __ldg(f + p) : 0.f;
            float tv = (p < P_) ? __ldg(t + p) : 0.f;
            fr[i] = fv; tr[i] = tv;
            sf2 += fv * fv;
            sft += fv * tv;
            st2 += tv * tv;
        }
#pragma unroll
        for (int off = 16; off; off >>= 1) {
            sf2 += __shfl_xor_sync(0xFFFFFFFFu, sf2, off);
            sft += __shfl_xor_sync(0xFFFFFFFFu, sft, off);
            st2 += __shfl_xor_sync(0xFFFFFFFFu, st2, off);
        }

        float norm  = sqrtf(sf2);
        float scale = (norm > 0.f) ? (atanhf(norm) / norm) : 1.0f;
        float x2 = scale * scale * sf2;
        float xy = scale * sft;
        float y2 = st2;
        float cu = 1.f + 2.f * xy + y2;
        float ct = 1.f - x2;
        float inv = 1.f / fmaxf(1.f + 2.f * xy + x2 * y2, 1e-15f);
        float alpha = cu * scale * inv;
        float beta  = ct * inv;
        if (gr >= KP1) { alpha = 0.f; beta = 0.f; }

        float* srow = stage + row * MST;
#pragma unroll
        for (int i = 0; i < 10; i++) {
            int p = lane + i * 32;
            srow[p] = tf32_rna(alpha * fr[i] + beta * tr[i]);
        }
    }
    __syncthreads();

    int t_  = mb >> 2;
    int tm  = mb & 3;
    float4* dstBase = (float4*)g_Mp;
#pragma unroll
    for (int h = 0; h < 5; h++) {
        int q   = tid + h * 256;
        int it  = q >> 7;
        int rem = q & 127;
        int kk  = rem >> 5;
        int ln  = rem & 31;
        int g   = ln >> 2;
        int tg  = ln & 3;
        int k0  = it * 32 + kk * 8 + tg;
        size_t di = ((size_t)(t_ * 10 + it) * 16 + kk * 4 + tm) * 32 + ln;
        dstBase[di] = make_float4(stage[g * MST + k0],     stage[(g + 8) * MST + k0],
                                  stage[g * MST + k0 + 4], stage[(g + 8) * MST + k0 + 4]);
    }
}

// ---------------------------------------------------------------------------
// Kernel 2: tf32 MMA GEMM (EXACT R8/R11/R12 config, 33us x4 measurements).
// ---------------------------------------------------------------------------
constexpr int BK    = 32;
constexpr int NIT   = PPAD / BK;
constexpr int A_ST  = 2048;
constexpr int B_ST  = 8192;
constexpr int SMEMF = 2 * (A_ST + B_ST);

__device__ __forceinline__ void cpa16(uint32_t dst, const float* src) {
    asm volatile("cp.async.cg.shared.global [%0], [%1], 16;" :: "r"(dst), "l"(src));
}

__global__ void __launch_bounds__(256) k_gemm(const float* __restrict__ bias) {
    extern __shared__ float sm[];
    float* Bsm[2] = { sm,            sm + B_ST };
    float* Asm[2] = { sm + 2 * B_ST, sm + 2 * B_ST + A_ST };

    int tid  = threadIdx.x;
    int warp = tid >> 5;
    int lane = tid & 31;
    int wm = warp >> 2;
    int wn = warp & 3;
    int g  = lane >> 2;
    int tg = lane & 3;
    int bt = blockIdx.x;
    int rowBase = bt * 64;

    auto load_stage = [&](int s, int it) {
        const float* Bsrc = g_Wp + (size_t)it * B_ST;
#pragma unroll
        for (int j = 0; j < 8; j++) {
            int c = (tid + j * 256) * 4;
            cpa16((uint32_t)__cvta_generic_to_shared(Bsm[s] + c), Bsrc + c);
        }
        const float* Asrc = g_Mp + ((size_t)bt * NIT + it) * A_ST;
#pragma unroll
        for (int j = 0; j < 2; j++) {
            int c = (tid + j * 256) * 4;
            cpa16((uint32_t)__cvta_generic_to_shared(Asm[s] + c), Asrc + c);
        }
    };

    float acc[2][8][4];
#pragma unroll
    for (int mi = 0; mi < 2; mi++)
#pragma unroll
        for (int ni = 0; ni < 8; ni++)
#pragma unroll
            for (int r = 0; r < 4; r++) acc[mi][ni][r] = 0.f;

    load_stage(0, 0);
    asm volatile("cp.async.commit_group;");

    for (int it = 0; it < NIT; it++) {
        int cur = it & 1;
        if (it + 1 < NIT) load_stage(cur ^ 1, it + 1);
        asm volatile("cp.async.commit_group;");
        asm volatile("cp.async.wait_group 1;");
        __syncthreads();

        const float* Ac = Asm[cur];
        const float* Bc = Bsm[cur];
#pragma unroll
        for (int kk = 0; kk < 4; kk++) {
            uint32_t a[2][4];
#pragma unroll
            for (int mi = 0; mi < 2; mi++) {
                float4 av = *(const float4*)(Ac + ((kk * 4 + wm * 2 + mi) * 32 + lane) * 4);
                a[mi][0] = __float_as_uint(av.x);
                a[mi][1] = __float_as_uint(av.y);
                a[mi][2] = __float_as_uint(av.z);
                a[mi][3] = __float_as_uint(av.w);
            }
#pragma unroll
            for (int ni = 0; ni < 8; ni++) {
                float2 bv = *(const float2*)(Bc + ((kk * 32 + wn * 8 + ni) * 32 + lane) * 2);
                uint32_t b0 = __float_as_uint(bv.x);
                uint32_t b1 = __float_as_uint(bv.y);
#pragma unroll
                for (int mi = 0; mi < 2; mi++) {
                    asm volatile(
                        "mma.sync.aligned.m16n8k8.row.col.f32.tf32.tf32.f32 "
                        "{%0,%1,%2,%3}, {%4,%5,%6,%7}, {%8,%9}, {%0,%1,%2,%3};"
                        : "+f"(acc[mi][ni][0]), "+f"(acc[mi][ni][1]),
                          "+f"(acc[mi][ni][2]), "+f"(acc[mi][ni][3])
                        : "r"(a[mi][0]), "r"(a[mi][1]), "r"(a[mi][2]), "r"(a[mi][3]),
                          "r"(b0), "r"(b1));
                }
            }
        }
        __syncthreads();
    }

#pragma unroll
    for (int mi = 0; mi < 2; mi++) {
#pragma unroll
        for (int ni = 0; ni < 8; ni++) {
            int col = wn * 64 + ni * 8 + tg * 2;
            float bx = __ldg(bias + col), by = __ldg(bias + col + 1);
            int r0 = rowBase + wm * 32 + mi * 16 + g;
            *(float2*)(g_T + (size_t)r0 * E_ + col) =
                make_float2(acc[mi][ni][0] + bx, acc[mi][ni][1] + by);
            *(float2*)(g_T + (size_t)(r0 + 8) * E_ + col) =
                make_float2(acc[mi][ni][2] + bx, acc[mi][ni][3] + by);
        }
    }
}

// ---------------------------------------------------------------------------
// Kernel 3a: regular tokens from compact list (Rw row + lin_b).
// 1 warp = 1 list entry; excess warps exit on one uniform counter load.
// ---------------------------------------------------------------------------
__global__ void __launch_bounds__(256) k_gather_reg(const float* __restrict__ Rw,
                                                    const float* __restrict__ lin_b,
                                                    float4* __restrict__ out) {
    int gtid = blockIdx.x * 256 + threadIdx.x;
    int w  = gtid >> 5;
    int e4 = gtid & 31;
    if (w >= g_cnt[1]) return;

    int2 e = __ldg(&g_lreg[w]);             // (tok, rm), warp-broadcast
    const float4* src = (const float4*)(Rw + (size_t)e.y * E_);
    float4 a0 = __ldg(src + e4);
    float4 a1 = __ldg(src + e4 + 32);
    float4 b0 = __ldg((const float4*)lin_b + e4);
    float4 b1 = __ldg((const float4*)lin_b + e4 + 32);

    float4* dst = out + (size_t)e.x * 64;
    __stcs(dst + e4,      make_float4(a0.x + b0.x, a0.y + b0.y, a0.z + b0.z, a0.w + b0.w));
    __stcs(dst + e4 + 32, make_float4(a1.x + b1.x, a1.y + b1.y, a1.z + b1.z, a1.w + b1.w));
}

// ---------------------------------------------------------------------------
// Kernel 3b: custom tokens from compact list (g_T row, bias folded in).
// ---------------------------------------------------------------------------
__global__ void __launch_bounds__(256) k_gather_cus(float4* __restrict__ out) {
    int gtid = blockIdx.x * 256 + threadIdx.x;
    int w  = gtid >> 5;
    int e4 = gtid & 31;
    if (w >= g_cnt[0]) return;

    int2 e = __ldg(&g_lcus[w]);             // (tok, cm)
    const float4* src = (const float4*)(g_T + (size_t)e.y * E_);
    float4 a0 = __ldg(src + e4);
    float4 a1 = __ldg(src + e4 + 32);

    float4* dst = out + (size_t)e.x * 64;
    __stcs(dst + e4,      a0);
    __stcs(dst + e4 + 32, a1);
}

// ---------------------------------------------------------------------------
// Launch. Inputs: 0:x 1:custom_indices(unused) 2:v2c 3:v2r
//  4:custom_fixed_w 5:custom_train_w 6:regular_w 7:lin_w 8:lin_b
// ---------------------------------------------------------------------------
extern "C" void kernel_launch(void* const* d_in, const int* in_sizes, int n_in,
                              void* d_out, int out_size) {
    const int*   x    = (const int*)d_in[0];
    const int*   v2c  = (const int*)d_in[2];
    const int*   v2r  = (const int*)d_in[3];
    const float* fw   = (const float*)d_in[4];
    const float* tw   = (const float*)d_in[5];
    const float* Rw   = (const float*)d_in[6];
    const float* W    = (const float*)d_in[7];
    const float* bias = (const float*)d_in[8];
    float4* out = (float4*)d_out;

    int ntok = in_sizes[0];

    static cudaStream_t s_side = nullptr;
    static cudaEvent_t  ev_fork = nullptr, ev_join = nullptr;
    if (!s_side) {
        cudaFuncSetAttribute(k_gemm, cudaFuncAttributeMaxDynamicSharedMemorySize,
                             SMEMF * (int)sizeof(float));
        cudaStreamCreateWithFlags(&s_side, cudaStreamNonBlocking);
        cudaEventCreateWithFlags(&ev_fork, cudaEventDisableTiming);
        cudaEventCreateWithFlags(&ev_join, cudaEventDisableTiming);
    }

    // fork side stream: custom-table chain (mobius -> wprep -> gemm)
    cudaEventRecord(ev_fork, 0);
    cudaStreamWaitEvent(s_side, ev_fork, 0);
    k_mobius<<<NMB, 256, 0, s_side>>>(fw, tw);
    k_wprep<<<(E_ * PPAD + 255) / 256, 256, 0, s_side>>>(W);
    k_gemm<<<NBT, 256, SMEMF * sizeof(float), s_side>>>(bias);
    cudaEventRecord(ev_join, s_side);

    // main stream: compaction + regular gather (DRAM-bound, overlaps side)
    k_zero<<<1, 32>>>();
    k_compact<<<(ntok + 255) / 256, 256>>>(x, v2c, v2r, ntok);
    int gblocks = (ntok * 32 + 255) / 256;
    k_gather_reg<<<gblocks, 256>>>(Rw, bias, out);

    // join, then custom gather from g_T
    cudaStreamWaitEvent(0, ev_join, 0);
    k_gather_cus<<<gblocks, 256>>>(out);
}

// round 14
// speedup vs baseline: 1.1262x; 1.1262x over previous
#include <cuda_runtime.h>
#include <cstdint>

// ---------------------------------------------------------------------------
// PoincareEmbeddings: out[b,l,:] = custom ? T[cm] : Rw[rm] + lin_b
// where T[k] = lin_w @ mobius_add(logmap0(fixed[k]), train[k]) + lin_b
//
// R14 = R12 (best measured structure, 121.6us) with ONE change: the GEMM's
// per-thread cp.async.cg stage copies (the measured ~21us overhead; LSU-bound
// at ~32B/cyc/SM) are replaced by single-thread cp.async.bulk (UBLKCP/TMA
// path) + mbarrier expect_tx. Both operand stages are contiguous in the
// fragment-permuted layouts, so each stage is exactly 2 bulk copies.
// Stream overlap is abandoned permanently (failed twice: R5 +15, R13 +14.6).
// ---------------------------------------------------------------------------

constexpr int P_    = 300;
constexpr int PPAD  = 320;
constexpr int E_    = 256;
constexpr int Kc    = 20000;
constexpr int KP1   = Kc + 1;
constexpr int KROWS = 20096;      // 314 * 64 == 1256 * 16
constexpr int NBT   = KROWS / 64; // 314 GEMM row-tiles
constexpr int NMB   = KROWS / 16; // 1256 mobius blocks
constexpr int VMAX  = 100000;

__device__ float g_Mp[(size_t)KROWS * PPAD];  // fragment-permuted mobius output
__device__ float g_T[(size_t)KROWS * E_];     // projected custom embeddings (+bias)
__device__ float g_Wp[(size_t)E_ * PPAD];     // lin_w, tf32, fragment-permuted
__device__ unsigned long long g_ptr[VMAX];    // per-vocab row pointer | custom flag

__device__ __forceinline__ float tf32_rna(float x) {
    float r;
    asm("cvt.rna.tf32.f32 %0, %1;" : "=f"(r) : "f"(x));
    return r;
}

// ---------------------------------------------------------------------------
// Prep A: lin_w -> g_Wp fragment-permuted tf32 (validated R7-R12).
// ---------------------------------------------------------------------------
__global__ void __launch_bounds__(256) k_wprep(const float* __restrict__ W) {
    int idx = blockIdx.x * 256 + threadIdx.x;
    if (idx >= E_ * PPAD) return;
    int slot = idx & 1;
    int lane = (idx >> 1) & 31;
    int t_n  = (idx >> 6) & 31;
    int t_k  = idx >> 11;
    int n = t_n * 8 + (lane >> 2);
    int k = t_k * 8 + (lane & 3) + slot * 4;
    g_Wp[idx] = (k < P_) ? tf32_rna(__ldg(W + (size_t)n * P_ + k)) : 0.f;
}

// ---------------------------------------------------------------------------
// Prep B: per-vocab fused row pointer (bit0 => custom row)
// ---------------------------------------------------------------------------
__global__ void __launch_bounds__(256) k_ptab(const int* __restrict__ v2c,
                                              const int* __restrict__ v2r,
                                              const float* __restrict__ Rw, int V) {
    int v = blockIdx.x * 256 + threadIdx.x;
    if (v >= V) return;
    int cm = __ldg(v2c + v);
    int rm = __ldg(v2r + v);
    unsigned long long p;
    if (cm) p = (unsigned long long)(g_T + (size_t)cm * E_) | 1ULL;
    else    p = (unsigned long long)(Rw  + (size_t)rm * E_);
    g_ptr[v] = p;
}

// ---------------------------------------------------------------------------
// Kernel 1: mobius -> fragment-permuted A (EXACT R12, measured ~14.5us).
// ---------------------------------------------------------------------------
constexpr int MST = 324;

__global__ void __launch_bounds__(256) k_mobius(const float* __restrict__ fixed_w,
                                                const float* __restrict__ train_w) {
    __shared__ float stage[16 * MST];

    int tid  = threadIdx.x;
    int warp = tid >> 5;
    int lane = tid & 31;
    int mb   = blockIdx.x;
    int rowBase = mb * 16;

#pragma unroll
    for (int r2 = 0; r2 < 2; r2++) {
        int row = warp * 2 + r2;
        int gr  = rowBase + row;
        int rs  = (gr < KP1) ? gr : 0;
        const float* f = fixed_w + (size_t)rs * P_;
        const float* t = train_w + (size_t)rs * P_;

        float fr[10], tr[10];
        float sf2 = 0.f, sft = 0.f, st2 = 0.f;
#pragma unroll
        for (int i = 0; i < 10; i++) {
            int p = lane + i * 32;
            float fv = (p < P_) ? __ldg(f + p) : 0.f;
            float tv = (p < P_) ? __ldg(t + p) : 0.f;
            fr[i] = fv; tr[i] = tv;
            sf2 += fv * fv;
            sft += fv * tv;
            st2 += tv * tv;
        }
#pragma unroll
        for (int off = 16; off; off >>= 1) {
            sf2 += __shfl_xor_sync(0xFFFFFFFFu, sf2, off);
            sft += __shfl_xor_sync(0xFFFFFFFFu, sft, off);
            st2 += __shfl_xor_sync(0xFFFFFFFFu, st2, off);
        }

        float norm  = sqrtf(sf2);
        float scale = (norm > 0.f) ? (atanhf(norm) / norm) : 1.0f;
        float x2 = scale * scale * sf2;
        float xy = scale * sft;
        float y2 = st2;
        float cu = 1.f + 2.f * xy + y2;
        float ct = 1.f - x2;
        float inv = 1.f / fmaxf(1.f + 2.f * xy + x2 * y2, 1e-15f);
        float alpha = cu * scale * inv;
        float beta  = ct * inv;
        if (gr >= KP1) { alpha = 0.f; beta = 0.f; }

        float* srow = stage + row * MST;
#pragma unroll
        for (int i = 0; i < 10; i++) {
            int p = lane + i * 32;
            srow[p] = tf32_rna(alpha * fr[i] + beta * tr[i]);
        }
    }
    __syncthreads();

    int t_  = mb >> 2;
    int tm  = mb & 3;
    float4* dstBase = (float4*)g_Mp;
#pragma unroll
    for (int h = 0; h < 5; h++) {
        int q   = tid + h * 256;
        int it  = q >> 7;
        int rem = q & 127;
        int kk  = rem >> 5;
        int ln  = rem & 31;
        int g   = ln >> 2;
        int tg  = ln & 3;
        int k0  = it * 32 + kk * 8 + tg;
        size_t di = ((size_t)(t_ * 10 + it) * 16 + kk * 4 + tm) * 32 + ln;
        dstBase[di] = make_float4(stage[g * MST + k0],     stage[(g + 8) * MST + k0],
                                  stage[g * MST + k0 + 4], stage[(g + 8) * MST + k0 + 4]);
    }
}

// ---------------------------------------------------------------------------
// Kernel 2: tf32 MMA GEMM with cp.async.bulk stage copies.
// BM=64 x BN=256, BK=32, 256 thr, 8 warps 2x4, warp 32x64, double-buffered.
// Stage copy = 2 bulk ops (B 32KB + A 8KB, both contiguous) issued by tid 0,
// completion via mbarrier expect_tx (40960 bytes). Buffer s at iteration it
// waits parity (it>>1)&1. End-of-MMA __syncthreads closes readers before the
// next overwrite of that buffer (R6 race lesson).
// ---------------------------------------------------------------------------
constexpr int BK    = 32;
constexpr int NIT   = PPAD / BK;      // 10
constexpr int A_ST  = 2048;           // floats
constexpr int B_ST  = 8192;           // floats
constexpr int SMEMF = 2 * (A_ST + B_ST);
constexpr unsigned STAGE_BYTES = (A_ST + B_ST) * 4;   // 40960

__device__ __forceinline__ void bulk_g2s(uint32_t dst_smem, const float* src,
                                         unsigned bytes, uint32_t mbar) {
    asm volatile(
        "cp.async.bulk.shared::cta.global.mbarrier::complete_tx::bytes "
        "[%0], [%1], %2, [%3];"
        :: "r"(dst_smem), "l"(src), "r"(bytes), "r"(mbar) : "memory");
}

__device__ __forceinline__ void mbar_wait(uint32_t mbar, unsigned parity) {
    asm volatile(
        "{\n\t"
        ".reg .pred P;\n\t"
        "WL_%=:\n\t"
        "mbarrier.try_wait.parity.acquire.cta.shared::cta.b64 P, [%0], %1, 0x989680;\n\t"
        "@P bra.uni WD_%=;\n\t"
        "bra.uni WL_%=;\n\t"
        "WD_%=:\n\t"
        "}"
        :: "r"(mbar), "r"(parity) : "memory");
}

__global__ void __launch_bounds__(256) k_gemm(const float* __restrict__ bias) {
    extern __shared__ float sm[];
    __shared__ __align__(8) unsigned long long mbar[2];

    float* Bsm[2] = { sm,            sm + B_ST };
    float* Asm[2] = { sm + 2 * B_ST, sm + 2 * B_ST + A_ST };

    int tid  = threadIdx.x;
    int warp = tid >> 5;
    int lane = tid & 31;
    int wm = warp >> 2;
    int wn = warp & 3;
    int g  = lane >> 2;
    int tg = lane & 3;
    int bt = blockIdx.x;
    int rowBase = bt * 64;

    uint32_t mb[2] = { (uint32_t)__cvta_generic_to_shared(&mbar[0]),
                       (uint32_t)__cvta_generic_to_shared(&mbar[1]) };
    if (tid == 0) {
        asm volatile("mbarrier.init.shared.b64 [%0], 1;" :: "r"(mb[0]) : "memory");
        asm volatile("mbarrier.init.shared.b64 [%0], 1;" :: "r"(mb[1]) : "memory");
    }
    __syncthreads();

    auto issue = [&](int s, int it) {   // tid 0 only
        asm volatile("mbarrier.arrive.expect_tx.shared.b64 _, [%0], %1;"
                     :: "r"(mb[s]), "r"(STAGE_BYTES) : "memory");
        bulk_g2s((uint32_t)__cvta_generic_to_shared(Bsm[s]),
                 g_Wp + (size_t)it * B_ST, B_ST * 4, mb[s]);
        bulk_g2s((uint32_t)__cvta_generic_to_shared(Asm[s]),
                 g_Mp + ((size_t)bt * NIT + it) * A_ST, A_ST * 4, mb[s]);
    };

    float acc[2][8][4];
#pragma unroll
    for (int mi = 0; mi < 2; mi++)
#pragma unroll
        for (int ni = 0; ni < 8; ni++)
#pragma unroll
            for (int r = 0; r < 4; r++) acc[mi][ni][r] = 0.f;

    if (tid == 0) issue(0, 0);

    for (int it = 0; it < NIT; it++) {
        int cur = it & 1;
        // Overwrite target buf cur^1: its readers (iter it-1) were closed by
        // the end-of-MMA __syncthreads; its previous phase completed at the
        // it-1 wait. Safe to issue now.
        if (tid == 0 && it + 1 < NIT) issue(cur ^ 1, it + 1);

        mbar_wait(mb[cur], (unsigned)((it >> 1) & 1));   // acquire: data visible

        const float* Ac = Asm[cur];
        const float* Bc = Bsm[cur];
#pragma unroll
        for (int kk = 0; kk < 4; kk++) {
            uint32_t a[2][4];
#pragma unroll
            for (int mi = 0; mi < 2; mi++) {
                float4 av = *(const float4*)(Ac + ((kk * 4 + wm * 2 + mi) * 32 + lane) * 4);
                a[mi][0] = __float_as_uint(av.x);
                a[mi][1] = __float_as_uint(av.y);
                a[mi][2] = __float_as_uint(av.z);
                a[mi][3] = __float_as_uint(av.w);
            }
#pragma unroll
            for (int ni = 0; ni < 8; ni++) {
                float2 bv = *(const float2*)(Bc + ((kk * 32 + wn * 8 + ni) * 32 + lane) * 2);
                uint32_t b0 = __float_as_uint(bv.x);
                uint32_t b1 = __float_as_uint(bv.y);
#pragma unroll
                for (int mi = 0; mi < 2; mi++) {
                    asm volatile(
                        "mma.sync.aligned.m16n8k8.row.col.f32.tf32.tf32.f32 "
                        "{%0,%1,%2,%3}, {%4,%5,%6,%7}, {%8,%9}, {%0,%1,%2,%3};"
                        : "+f"(acc[mi][ni][0]), "+f"(acc[mi][ni][1]),
                          "+f"(acc[mi][ni][2]), "+f"(acc[mi][ni][3])
                        : "r"(a[mi][0]), "r"(a[mi][1]), "r"(a[mi][2]), "r"(a[mi][3]),
                          "r"(b0), "r"(b1));
                }
            }
        }
        __syncthreads();   // close readers before next overwrite of this buffer
    }

#pragma unroll
    for (int mi = 0; mi < 2; mi++) {
#pragma unroll
        for (int ni = 0; ni < 8; ni++) {
            int col = wn * 64 + ni * 8 + tg * 2;
            float bx = __ldg(bias + col), by = __ldg(bias + col + 1);
            int r0 = rowBase + wm * 32 + mi * 16 + g;
            *(float2*)(g_T + (size_t)r0 * E_ + col) =
                make_float2(acc[mi][ni][0] + bx, acc[mi][ni][1] + by);
            *(float2*)(g_T + (size_t)(r0 + 8) * E_ + col) =
                make_float2(acc[mi][ni][2] + bx, acc[mi][ni][3] + by);
        }
    }
}

// ---------------------------------------------------------------------------
// Kernel 3: gather (EXACT R12, measured 69us at its traffic roofline).
// ---------------------------------------------------------------------------
__global__ void __launch_bounds__(256) k_gather(const int* __restrict__ x,
                                                const float* __restrict__ lin_b,
                                                float4* __restrict__ out,
                                                int ntok) {
    int gtid = blockIdx.x * 256 + threadIdx.x;
    int tok = gtid >> 5;
    int e4  = gtid & 31;
    if (tok >= ntok) return;

    int v = __ldg(x + tok);
    unsigned long long t = __ldg(g_ptr + v);
    float s = (t & 1ULL) ? 0.f : 1.f;
    const float4* src = (const float4*)(t & ~1ULL);

    float4 a0 = __ldg(src + e4);
    float4 a1 = __ldg(src + e4 + 32);
    float4 b0 = __ldg((const float4*)lin_b + e4);
    float4 b1 = __ldg((const float4*)lin_b + e4 + 32);

    float4* dst = out + (size_t)tok * 64;
    __stcs(dst + e4,      make_float4(a0.x + s * b0.x, a0.y + s * b0.y,
                                      a0.z + s * b0.z, a0.w + s * b0.w));
    __stcs(dst + e4 + 32, make_float4(a1.x + s * b1.x, a1.y + s * b1.y,
                                      a1.z + s * b1.z, a1.w + s * b1.w));
}

// ---------------------------------------------------------------------------
// Launch (single stream, R12 structure). Inputs: 0:x 1:custom_indices(unused)
//  2:v2c 3:v2r 4:custom_fixed_w 5:custom_train_w 6:regular_w 7:lin_w 8:lin_b
// ---------------------------------------------------------------------------
extern "C" void kernel_launch(void* const* d_in, const int* in_sizes, int n_in,
                              void* d_out, int out_size) {
    const int*   x    = (const int*)d_in[0];
    const int*   v2c  = (const int*)d_in[2];
    const int*   v2r  = (const int*)d_in[3];
    const float* fw   = (const float*)d_in[4];
    const float* tw   = (const float*)d_in[5];
    const float* Rw   = (const float*)d_in[6];
    const float* W    = (const float*)d_in[7];
    const float* bias = (const float*)d_in[8];
    float4* out = (float4*)d_out;

    int ntok = in_sizes[0];
    int V    = in_sizes[2];

    static bool init_done = false;
    if (!init_done) {
        cudaFuncSetAttribute(k_gemm, cudaFuncAttributeMaxDynamicSharedMemorySize,
                             SMEMF * (int)sizeof(float));
        init_done = true;
    }

    k_wprep<<<(E_ * PPAD + 255) / 256, 256>>>(W);
    k_ptab<<<(V + 255) / 256, 256>>>(v2c, v2r, Rw, V);
    k_mobius<<<NMB, 256>>>(fw, tw);
    k_gemm<<<NBT, 256, SMEMF * sizeof(float)>>>(bias);

    int gthreads = ntok * 32;
    k_gather<<<(gthreads + 255) / 256, 256>>>(x, bias, out, ntok);
}

// round 15
// speedup vs baseline: 1.1855x; 1.0526x over previous
#include <cuda_runtime.h>
#include <cstdint>

// ---------------------------------------------------------------------------
// PoincareEmbeddings: out[b,l,:] = custom ? T[cm] : Rw[rm] + lin_b
// where T[k] = lin_w @ mobius_add(logmap0(fixed[k]), train[k]) + lin_b
//
// R15 = R14 with the three independent prelude kernels (mobius, wprep, ptab)
// MERGED into one launch (branch on blockIdx) to remove two launch gaps
// (empty-kernel cost measured at 3.7us in R13). GEMM (32.7us, 5 variants
// bracketed) and gather (69us, DRAM roofline) unchanged.
// ---------------------------------------------------------------------------

constexpr int P_    = 300;
constexpr int PPAD  = 320;
constexpr int E_    = 256;
constexpr int Kc    = 20000;
constexpr int KP1   = Kc + 1;
constexpr int KROWS = 20096;      // 314 * 64 == 1256 * 16
constexpr int NBT   = KROWS / 64; // 314 GEMM row-tiles
constexpr int NMB   = KROWS / 16; // 1256 mobius blocks
constexpr int VMAX  = 100000;

constexpr int WPREP_BLKS = (E_ * PPAD + 255) / 256;   // 320
constexpr int PTAB_BLKS  = (VMAX + 255) / 256;        // 391

__device__ float g_Mp[(size_t)KROWS * PPAD];  // fragment-permuted mobius output
__device__ float g_T[(size_t)KROWS * E_];     // projected custom embeddings (+bias)
__device__ float g_Wp[(size_t)E_ * PPAD];     // lin_w, tf32, fragment-permuted
__device__ unsigned long long g_ptr[VMAX];    // per-vocab row pointer | custom flag

__device__ __forceinline__ float tf32_rna(float x) {
    float r;
    asm("cvt.rna.tf32.f32 %0, %1;" : "=f"(r) : "f"(x));
    return r;
}

// ---------------------------------------------------------------------------
// Fused prelude: blockIdx < NMB           -> mobius (R12/R14 code, verbatim)
//                NMB..NMB+WPREP_BLKS      -> wprep  (verbatim)
//                rest                      -> ptab  (verbatim)
// All three branches are independent; smem is used only by the mobius branch.
// ---------------------------------------------------------------------------
constexpr int MST = 324;

__global__ void __launch_bounds__(256) k_prelude(const float* __restrict__ fixed_w,
                                                 const float* __restrict__ train_w,
                                                 const float* __restrict__ W,
                                                 const int* __restrict__ v2c,
                                                 const int* __restrict__ v2r,
                                                 const float* __restrict__ Rw,
                                                 int V) {
    __shared__ float stage[16 * MST];
    int bid = blockIdx.x;
    int tid = threadIdx.x;

    if (bid >= NMB) {
        int sb = bid - NMB;
        if (sb < WPREP_BLKS) {
            // ---- wprep branch ----
            int idx = sb * 256 + tid;
            if (idx < E_ * PPAD) {
                int slot = idx & 1;
                int lane = (idx >> 1) & 31;
                int t_n  = (idx >> 6) & 31;
                int t_k  = idx >> 11;
                int n = t_n * 8 + (lane >> 2);
                int k = t_k * 8 + (lane & 3) + slot * 4;
                g_Wp[idx] = (k < P_) ? tf32_rna(__ldg(W + (size_t)n * P_ + k)) : 0.f;
            }
        } else {
            // ---- ptab branch ----
            int v = (sb - WPREP_BLKS) * 256 + tid;
            if (v < V) {
                int cm = __ldg(v2c + v);
                int rm = __ldg(v2r + v);
                unsigned long long p;
                if (cm) p = (unsigned long long)(g_T + (size_t)cm * E_) | 1ULL;
                else    p = (unsigned long long)(Rw  + (size_t)rm * E_);
                g_ptr[v] = p;
            }
        }
        return;
    }

    // ---- mobius branch (R12/R14 verbatim) ----
    int warp = tid >> 5;
    int lane = tid & 31;
    int mb   = bid;
    int rowBase = mb * 16;

#pragma unroll
    for (int r2 = 0; r2 < 2; r2++) {
        int row = warp * 2 + r2;
        int gr  = rowBase + row;
        int rs  = (gr < KP1) ? gr : 0;
        const float* f = fixed_w + (size_t)rs * P_;
        const float* t = train_w + (size_t)rs * P_;

        float fr[10], tr[10];
        float sf2 = 0.f, sft = 0.f, st2 = 0.f;
#pragma unroll
        for (int i = 0; i < 10; i++) {
            int p = lane + i * 32;
            float fv = (p < P_) ? __ldg(f + p) : 0.f;
            float tv = (p < P_) ? __ldg(t + p) : 0.f;
            fr[i] = fv; tr[i] = tv;
            sf2 += fv * fv;
            sft += fv * tv;
            st2 += tv * tv;
        }
#pragma unroll
        for (int off = 16; off; off >>= 1) {
            sf2 += __shfl_xor_sync(0xFFFFFFFFu, sf2, off);
            sft += __shfl_xor_sync(0xFFFFFFFFu, sft, off);
            st2 += __shfl_xor_sync(0xFFFFFFFFu, st2, off);
        }

        float norm  = sqrtf(sf2);
        float scale = (norm > 0.f) ? (atanhf(norm) / norm) : 1.0f;
        float x2 = scale * scale * sf2;
        float xy = scale * sft;
        float y2 = st2;
        float cu = 1.f + 2.f * xy + y2;
        float ct = 1.f - x2;
        float inv = 1.f / fmaxf(1.f + 2.f * xy + x2 * y2, 1e-15f);
        float alpha = cu * scale * inv;
        float beta  = ct * inv;
        if (gr >= KP1) { alpha = 0.f; beta = 0.f; }

        float* srow = stage + row * MST;
#pragma unroll
        for (int i = 0; i < 10; i++) {
            int p = lane + i * 32;
            srow[p] = tf32_rna(alpha * fr[i] + beta * tr[i]);
        }
    }
    __syncthreads();

    int t_  = mb >> 2;
    int tm  = mb & 3;
    float4* dstBase = (float4*)g_Mp;
#pragma unroll
    for (int h = 0; h < 5; h++) {
        int q   = tid + h * 256;
        int it  = q >> 7;
        int rem = q & 127;
        int kk  = rem >> 5;
        int ln  = rem & 31;
        int g   = ln >> 2;
        int tg  = ln & 3;
        int k0  = it * 32 + kk * 8 + tg;
        size_t di = ((size_t)(t_ * 10 + it) * 16 + kk * 4 + tm) * 32 + ln;
        dstBase[di] = make_float4(stage[g * MST + k0],     stage[(g + 8) * MST + k0],
                                  stage[g * MST + k0 + 4], stage[(g + 8) * MST + k0 + 4]);
    }
}

// ---------------------------------------------------------------------------
// Kernel 2: tf32 MMA GEMM with cp.async.bulk stage copies (EXACT R14, 32.7us).
// ---------------------------------------------------------------------------
constexpr int BK    = 32;
constexpr int NIT   = PPAD / BK;      // 10
constexpr int A_ST  = 2048;           // floats
constexpr int B_ST  = 8192;           // floats
constexpr int SMEMF = 2 * (A_ST + B_ST);
constexpr unsigned STAGE_BYTES = (A_ST + B_ST) * 4;   // 40960

__device__ __forceinline__ void bulk_g2s(uint32_t dst_smem, const float* src,
                                         unsigned bytes, uint32_t mbar) {
    asm volatile(
        "cp.async.bulk.shared::cta.global.mbarrier::complete_tx::bytes "
        "[%0], [%1], %2, [%3];"
        :: "r"(dst_smem), "l"(src), "r"(bytes), "r"(mbar) : "memory");
}

__device__ __forceinline__ void mbar_wait(uint32_t mbar, unsigned parity) {
    asm volatile(
        "{\n\t"
        ".reg .pred P;\n\t"
        "WL_%=:\n\t"
        "mbarrier.try_wait.parity.acquire.cta.shared::cta.b64 P, [%0], %1, 0x989680;\n\t"
        "@P bra.uni WD_%=;\n\t"
        "bra.uni WL_%=;\n\t"
        "WD_%=:\n\t"
        "}"
        :: "r"(mbar), "r"(parity) : "memory");
}

__global__ void __launch_bounds__(256) k_gemm(const float* __restrict__ bias) {
    extern __shared__ float sm[];
    __shared__ __align__(8) unsigned long long mbar[2];

    float* Bsm[2] = { sm,            sm + B_ST };
    float* Asm[2] = { sm + 2 * B_ST, sm + 2 * B_ST + A_ST };

    int tid  = threadIdx.x;
    int warp = tid >> 5;
    int lane = tid & 31;
    int wm = warp >> 2;
    int wn = warp & 3;
    int g  = lane >> 2;
    int tg = lane & 3;
    int bt = blockIdx.x;
    int rowBase = bt * 64;

    uint32_t mb[2] = { (uint32_t)__cvta_generic_to_shared(&mbar[0]),
                       (uint32_t)__cvta_generic_to_shared(&mbar[1]) };
    if (tid == 0) {
        asm volatile("mbarrier.init.shared.b64 [%0], 1;" :: "r"(mb[0]) : "memory");
        asm volatile("mbarrier.init.shared.b64 [%0], 1;" :: "r"(mb[1]) : "memory");
    }
    __syncthreads();

    auto issue = [&](int s, int it) {   // tid 0 only
        asm volatile("mbarrier.arrive.expect_tx.shared.b64 _, [%0], %1;"
                     :: "r"(mb[s]), "r"(STAGE_BYTES) : "memory");
        bulk_g2s((uint32_t)__cvta_generic_to_shared(Bsm[s]),
                 g_Wp + (size_t)it * B_ST, B_ST * 4, mb[s]);
        bulk_g2s((uint32_t)__cvta_generic_to_shared(Asm[s]),
                 g_Mp + ((size_t)bt * NIT + it) * A_ST, A_ST * 4, mb[s]);
    };

    float acc[2][8][4];
#pragma unroll
    for (int mi = 0; mi < 2; mi++)
#pragma unroll
        for (int ni = 0; ni < 8; ni++)
#pragma unroll
            for (int r = 0; r < 4; r++) acc[mi][ni][r] = 0.f;

    if (tid == 0) issue(0, 0);

    for (int it = 0; it < NIT; it++) {
        int cur = it & 1;
        if (tid == 0 && it + 1 < NIT) issue(cur ^ 1, it + 1);

        mbar_wait(mb[cur], (unsigned)((it >> 1) & 1));

        const float* Ac = Asm[cur];
        const float* Bc = Bsm[cur];
#pragma unroll
        for (int kk = 0; kk < 4; kk++) {
            uint32_t a[2][4];
#pragma unroll
            for (int mi = 0; mi < 2; mi++) {
                float4 av = *(const float4*)(Ac + ((kk * 4 + wm * 2 + mi) * 32 + lane) * 4);
                a[mi][0] = __float_as_uint(av.x);
                a[mi][1] = __float_as_uint(av.y);
                a[mi][2] = __float_as_uint(av.z);
                a[mi][3] = __float_as_uint(av.w);
            }
#pragma unroll
            for (int ni = 0; ni < 8; ni++) {
                float2 bv = *(const float2*)(Bc + ((kk * 32 + wn * 8 + ni) * 32 + lane) * 2);
                uint32_t b0 = __float_as_uint(bv.x);
                uint32_t b1 = __float_as_uint(bv.y);
#pragma unroll
                for (int mi = 0; mi < 2; mi++) {
                    asm volatile(
                        "mma.sync.aligned.m16n8k8.row.col.f32.tf32.tf32.f32 "
                        "{%0,%1,%2,%3}, {%4,%5,%6,%7}, {%8,%9}, {%0,%1,%2,%3};"
                        : "+f"(acc[mi][ni][0]), "+f"(acc[mi][ni][1]),
                          "+f"(acc[mi][ni][2]), "+f"(acc[mi][ni][3])
                        : "r"(a[mi][0]), "r"(a[mi][1]), "r"(a[mi][2]), "r"(a[mi][3]),
                          "r"(b0), "r"(b1));
                }
            }
        }
        __syncthreads();   // close readers before next overwrite of this buffer
    }

#pragma unroll
    for (int mi = 0; mi < 2; mi++) {
#pragma unroll
        for (int ni = 0; ni < 8; ni++) {
            int col = wn * 64 + ni * 8 + tg * 2;
            float bx = __ldg(bias + col), by = __ldg(bias + col + 1);
            int r0 = rowBase + wm * 32 + mi * 16 + g;
            *(float2*)(g_T + (size_t)r0 * E_ + col) =
                make_float2(acc[mi][ni][0] + bx, acc[mi][ni][1] + by);
            *(float2*)(g_T + (size_t)(r0 + 8) * E_ + col) =
                make_float2(acc[mi][ni][2] + bx, acc[mi][ni][3] + by);
        }
    }
}

// ---------------------------------------------------------------------------
// Kernel 3: gather (EXACT R12/R14, 69us, DRAM roofline).
// ---------------------------------------------------------------------------
__global__ void __launch_bounds__(256) k_gather(const int* __restrict__ x,
                                                const float* __restrict__ lin_b,
                                                float4* __restrict__ out,
                                                int ntok) {
    int gtid = blockIdx.x * 256 + threadIdx.x;
    int tok = gtid >> 5;
    int e4  = gtid & 31;
    if (tok >= ntok) return;

    int v = __ldg(x + tok);
    unsigned long long t = __ldg(g_ptr + v);
    float s = (t & 1ULL) ? 0.f : 1.f;
    const float4* src = (const float4*)(t & ~1ULL);

    float4 a0 = __ldg(src + e4);
    float4 a1 = __ldg(src + e4 + 32);
    float4 b0 = __ldg((const float4*)lin_b + e4);
    float4 b1 = __ldg((const float4*)lin_b + e4 + 32);

    float4* dst = out + (size_t)tok * 64;
    __stcs(dst + e4,      make_float4(a0.x + s * b0.x, a0.y + s * b0.y,
                                      a0.z + s * b0.z, a0.w + s * b0.w));
    __stcs(dst + e4 + 32, make_float4(a1.x + s * b1.x, a1.y + s * b1.y,
                                      a1.z + s * b1.z, a1.w + s * b1.w));
}

// ---------------------------------------------------------------------------
// Launch (3 kernels total). Inputs: 0:x 1:custom_indices(unused) 2:v2c 3:v2r
//  4:custom_fixed_w 5:custom_train_w 6:regular_w 7:lin_w 8:lin_b
// ---------------------------------------------------------------------------
extern "C" void kernel_launch(void* const* d_in, const int* in_sizes, int n_in,
                              void* d_out, int out_size) {
    const int*   x    = (const int*)d_in[0];
    const int*   v2c  = (const int*)d_in[2];
    const int*   v2r  = (const int*)d_in[3];
    const float* fw   = (const float*)d_in[4];
    const float* tw   = (const float*)d_in[5];
    const float* Rw   = (const float*)d_in[6];
    const float* W    = (const float*)d_in[7];
    const float* bias = (const float*)d_in[8];
    float4* out = (float4*)d_out;

    int ntok = in_sizes[0];
    int V    = in_sizes[2];

    static bool init_done = false;
    if (!init_done) {
        cudaFuncSetAttribute(k_gemm, cudaFuncAttributeMaxDynamicSharedMemorySize,
                             SMEMF * (int)sizeof(float));
        init_done = true;
    }

    k_prelude<<<NMB + WPREP_BLKS + PTAB_BLKS, 256>>>(fw, tw, W, v2c, v2r, Rw, V);
    k_gemm<<<NBT, 256, SMEMF * sizeof(float)>>>(bias);

    int gthreads = ntok * 32;
    k_gather<<<(gthreads + 255) / 256, 256>>>(x, bias, out, ntok);
}

// round 16
// speedup vs baseline: 1.2033x; 1.0150x over previous
#include <cuda_runtime.h>
#include <cstdint>

// ---------------------------------------------------------------------------
// PoincareEmbeddings: out[b,l,:] = custom ? T[cm] : Rw[rm] + lin_b
// where T[k] = lin_w @ mobius_add(logmap0(fixed[k]), train[k]) + lin_b
//
// R16 = R15 with the vocab-indexed pointer table (g_ptr) replaced by a
// TOKEN-indexed one (g_tokptr), computed in the fused prelude directly from
// x/v2c/v2r. The gather's per-warp dependent chain drops from two serialized
// L2 hops (x[tok] -> g_ptr[v]) to one (g_tokptr[tok]), doubling effective
// read MLP in its measured latency-limited regime (issue=15.8%).
// ---------------------------------------------------------------------------

constexpr int P_    = 300;
constexpr int PPAD  = 320;
constexpr int E_    = 256;
constexpr int Kc    = 20000;
constexpr int KP1   = Kc + 1;
constexpr int KROWS = 20096;      // 314 * 64 == 1256 * 16
constexpr int NBT   = KROWS / 64; // 314 GEMM row-tiles
constexpr int NMB   = KROWS / 16; // 1256 mobius blocks
constexpr int NTOKMAX = 262144;

constexpr int WPREP_BLKS = (E_ * PPAD + 255) / 256;   // 320

__device__ float g_Mp[(size_t)KROWS * PPAD];  // fragment-permuted mobius output
__device__ float g_T[(size_t)KROWS * E_];     // projected custom embeddings (+bias)
__device__ float g_Wp[(size_t)E_ * PPAD];     // lin_w, tf32, fragment-permuted
__device__ unsigned long long g_tokptr[NTOKMAX]; // per-TOKEN row pointer | custom flag

__device__ __forceinline__ float tf32_rna(float x) {
    float r;
    asm("cvt.rna.tf32.f32 %0, %1;" : "=f"(r) : "f"(x));
    return r;
}

// ---------------------------------------------------------------------------
// Fused prelude: blockIdx < NMB            -> mobius (verbatim R12-R15)
//                NMB..NMB+WPREP_BLKS       -> wprep  (verbatim)
//                rest                       -> tokptr (per-token row pointer)
// ---------------------------------------------------------------------------
constexpr int MST = 324;

__global__ void __launch_bounds__(256) k_prelude(const float* __restrict__ fixed_w,
                                                 const float* __restrict__ train_w,
                                                 const float* __restrict__ W,
                                                 const int* __restrict__ x,
                                                 const int* __restrict__ v2c,
                                                 const int* __restrict__ v2r,
                                                 const float* __restrict__ Rw,
                                                 int ntok) {
    __shared__ float stage[16 * MST];
    int bid = blockIdx.x;
    int tid = threadIdx.x;

    if (bid >= NMB) {
        int sb = bid - NMB;
        if (sb < WPREP_BLKS) {
            // ---- wprep branch ----
            int idx = sb * 256 + tid;
            if (idx < E_ * PPAD) {
                int slot = idx & 1;
                int lane = (idx >> 1) & 31;
                int t_n  = (idx >> 6) & 31;
                int t_k  = idx >> 11;
                int n = t_n * 8 + (lane >> 2);
                int k = t_k * 8 + (lane & 3) + slot * 4;
                g_Wp[idx] = (k < P_) ? tf32_rna(__ldg(W + (size_t)n * P_ + k)) : 0.f;
            }
        } else {
            // ---- tokptr branch: per-token fused row pointer ----
            int tok = (sb - WPREP_BLKS) * 256 + tid;
            if (tok < ntok) {
                int v  = __ldg(x + tok);
                int cm = __ldg(v2c + v);
                unsigned long long p;
                if (cm) {
                    p = (unsigned long long)(g_T + (size_t)cm * E_) | 1ULL;
                } else {
                    int rm = __ldg(v2r + v);
                    p = (unsigned long long)(Rw + (size_t)rm * E_);
                }
                g_tokptr[tok] = p;
            }
        }
        return;
    }

    // ---- mobius branch (verbatim R12-R15, measured ~14.5us standalone) ----
    int warp = tid >> 5;
    int lane = tid & 31;
    int mb   = bid;
    int rowBase = mb * 16;

#pragma unroll
    for (int r2 = 0; r2 < 2; r2++) {
        int row = warp * 2 + r2;
        int gr  = rowBase + row;
        int rs  = (gr < KP1) ? gr : 0;
        const float* f = fixed_w + (size_t)rs * P_;
        const float* t = train_w + (size_t)rs * P_;

        float fr[10], tr[10];
        float sf2 = 0.f, sft = 0.f, st2 = 0.f;
#pragma unroll
        for (int i = 0; i < 10; i++) {
            int p = lane + i * 32;
            float fv = (p < P_) ? __ldg(f + p) : 0.f;
            float tv = (p < P_) ? __ldg(t + p) : 0.f;
            fr[i] = fv; tr[i] = tv;
            sf2 += fv * fv;
            sft += fv * tv;
            st2 += tv * tv;
        }
#pragma unroll
        for (int off = 16; off; off >>= 1) {
            sf2 += __shfl_xor_sync(0xFFFFFFFFu, sf2, off);
            sft += __shfl_xor_sync(0xFFFFFFFFu, sft, off);
            st2 += __shfl_xor_sync(0xFFFFFFFFu, st2, off);
        }

        float norm  = sqrtf(sf2);
        float scale = (norm > 0.f) ? (atanhf(norm) / norm) : 1.0f;
        float x2 = scale * scale * sf2;
        float xy = scale * sft;
        float y2 = st2;
        float cu = 1.f + 2.f * xy + y2;
        float ct = 1.f - x2;
        float inv = 1.f / fmaxf(1.f + 2.f * xy + x2 * y2, 1e-15f);
        float alpha = cu * scale * inv;
        float beta  = ct * inv;
        if (gr >= KP1) { alpha = 0.f; beta = 0.f; }

        float* srow = stage + row * MST;
#pragma unroll
        for (int i = 0; i < 10; i++) {
            int p = lane + i * 32;
            srow[p] = tf32_rna(alpha * fr[i] + beta * tr[i]);
        }
    }
    __syncthreads();

    int t_  = mb >> 2;
    int tm  = mb & 3;
    float4* dstBase = (float4*)g_Mp;
#pragma unroll
    for (int h = 0; h < 5; h++) {
        int q   = tid + h * 256;
        int it  = q >> 7;
        int rem = q & 127;
        int kk  = rem >> 5;
        int ln  = rem & 31;
        int g   = ln >> 2;
        int tg  = ln & 3;
        int k0  = it * 32 + kk * 8 + tg;
        size_t di = ((size_t)(t_ * 10 + it) * 16 + kk * 4 + tm) * 32 + ln;
        dstBase[di] = make_float4(stage[g * MST + k0],     stage[(g + 8) * MST + k0],
                                  stage[g * MST + k0 + 4], stage[(g + 8) * MST + k0 + 4]);
    }
}

// ---------------------------------------------------------------------------
// Kernel 2: tf32 MMA GEMM with cp.async.bulk stage copies (EXACT R14/R15).
// ---------------------------------------------------------------------------
constexpr int BK    = 32;
constexpr int NIT   = PPAD / BK;      // 10
constexpr int A_ST  = 2048;           // floats
constexpr int B_ST  = 8192;           // floats
constexpr int SMEMF = 2 * (A_ST + B_ST);
constexpr unsigned STAGE_BYTES = (A_ST + B_ST) * 4;   // 40960

__device__ __forceinline__ void bulk_g2s(uint32_t dst_smem, const float* src,
                                         unsigned bytes, uint32_t mbar) {
    asm volatile(
        "cp.async.bulk.shared::cta.global.mbarrier::complete_tx::bytes "
        "[%0], [%1], %2, [%3];"
        :: "r"(dst_smem), "l"(src), "r"(bytes), "r"(mbar) : "memory");
}

__device__ __forceinline__ void mbar_wait(uint32_t mbar, unsigned parity) {
    asm volatile(
        "{\n\t"
        ".reg .pred P;\n\t"
        "WL_%=:\n\t"
        "mbarrier.try_wait.parity.acquire.cta.shared::cta.b64 P, [%0], %1, 0x989680;\n\t"
        "@P bra.uni WD_%=;\n\t"
        "bra.uni WL_%=;\n\t"
        "WD_%=:\n\t"
        "}"
        :: "r"(mbar), "r"(parity) : "memory");
}

__global__ void __launch_bounds__(256) k_gemm(const float* __restrict__ bias) {
    extern __shared__ float sm[];
    __shared__ __align__(8) unsigned long long mbar[2];

    float* Bsm[2] = { sm,            sm + B_ST };
    float* Asm[2] = { sm + 2 * B_ST, sm + 2 * B_ST + A_ST };

    int tid  = threadIdx.x;
    int warp = tid >> 5;
    int lane = tid & 31;
    int wm = warp >> 2;
    int wn = warp & 3;
    int g  = lane >> 2;
    int tg = lane & 3;
    int bt = blockIdx.x;
    int rowBase = bt * 64;

    uint32_t mb[2] = { (uint32_t)__cvta_generic_to_shared(&mbar[0]),
                       (uint32_t)__cvta_generic_to_shared(&mbar[1]) };
    if (tid == 0) {
        asm volatile("mbarrier.init.shared.b64 [%0], 1;" :: "r"(mb[0]) : "memory");
        asm volatile("mbarrier.init.shared.b64 [%0], 1;" :: "r"(mb[1]) : "memory");
    }
    __syncthreads();

    auto issue = [&](int s, int it) {   // tid 0 only
        asm volatile("mbarrier.arrive.expect_tx.shared.b64 _, [%0], %1;"
                     :: "r"(mb[s]), "r"(STAGE_BYTES) : "memory");
        bulk_g2s((uint32_t)__cvta_generic_to_shared(Bsm[s]),
                 g_Wp + (size_t)it * B_ST, B_ST * 4, mb[s]);
        bulk_g2s((uint32_t)__cvta_generic_to_shared(Asm[s]),
                 g_Mp + ((size_t)bt * NIT + it) * A_ST, A_ST * 4, mb[s]);
    };

    float acc[2][8][4];
#pragma unroll
    for (int mi = 0; mi < 2; mi++)
#pragma unroll
        for (int ni = 0; ni < 8; ni++)
#pragma unroll
            for (int r = 0; r < 4; r++) acc[mi][ni][r] = 0.f;

    if (tid == 0) issue(0, 0);

    for (int it = 0; it < NIT; it++) {
        int cur = it & 1;
        if (tid == 0 && it + 1 < NIT) issue(cur ^ 1, it + 1);

        mbar_wait(mb[cur], (unsigned)((it >> 1) & 1));

        const float* Ac = Asm[cur];
        const float* Bc = Bsm[cur];
#pragma unroll
        for (int kk = 0; kk < 4; kk++) {
            uint32_t a[2][4];
#pragma unroll
            for (int mi = 0; mi < 2; mi++) {
                float4 av = *(const float4*)(Ac + ((kk * 4 + wm * 2 + mi) * 32 + lane) * 4);
                a[mi][0] = __float_as_uint(av.x);
                a[mi][1] = __float_as_uint(av.y);
                a[mi][2] = __float_as_uint(av.z);
                a[mi][3] = __float_as_uint(av.w);
            }
#pragma unroll
            for (int ni = 0; ni < 8; ni++) {
                float2 bv = *(const float2*)(Bc + ((kk * 32 + wn * 8 + ni) * 32 + lane) * 2);
                uint32_t b0 = __float_as_uint(bv.x);
                uint32_t b1 = __float_as_uint(bv.y);
#pragma unroll
                for (int mi = 0; mi < 2; mi++) {
                    asm volatile(
                        "mma.sync.aligned.m16n8k8.row.col.f32.tf32.tf32.f32 "
                        "{%0,%1,%2,%3}, {%4,%5,%6,%7}, {%8,%9}, {%0,%1,%2,%3};"
                        : "+f"(acc[mi][ni][0]), "+f"(acc[mi][ni][1]),
                          "+f"(acc[mi][ni][2]), "+f"(acc[mi][ni][3])
                        : "r"(a[mi][0]), "r"(a[mi][1]), "r"(a[mi][2]), "r"(a[mi][3]),
                          "r"(b0), "r"(b1));
                }
            }
        }
        __syncthreads();   // close readers before next overwrite of this buffer
    }

#pragma unroll
    for (int mi = 0; mi < 2; mi++) {
#pragma unroll
        for (int ni = 0; ni < 8; ni++) {
            int col = wn * 64 + ni * 8 + tg * 2;
            float bx = __ldg(bias + col), by = __ldg(bias + col + 1);
            int r0 = rowBase + wm * 32 + mi * 16 + g;
            *(float2*)(g_T + (size_t)r0 * E_ + col) =
                make_float2(acc[mi][ni][0] + bx, acc[mi][ni][1] + by);
            *(float2*)(g_T + (size_t)(r0 + 8) * E_ + col) =
                make_float2(acc[mi][ni][2] + bx, acc[mi][ni][3] + by);
        }
    }
}

// ---------------------------------------------------------------------------
// Kernel 3: gather with single-hop pointer chain: g_tokptr[tok] -> row.
// 1 warp = 1 token, 2 float4/lane, streaming stores (proven arithmetic).
// ---------------------------------------------------------------------------
__global__ void __launch_bounds__(256) k_gather(const float* __restrict__ lin_b,
                                                float4* __restrict__ out,
                                                int ntok) {
    int gtid = blockIdx.x * 256 + threadIdx.x;
    int tok = gtid >> 5;
    int e4  = gtid & 31;
    if (tok >= ntok) return;

    unsigned long long t = __ldg(g_tokptr + tok);   // ONE uniform hop
    float s = (t & 1ULL) ? 0.f : 1.f;
    const float4* src = (const float4*)(t & ~1ULL);

    float4 a0 = __ldg(src + e4);
    float4 a1 = __ldg(src + e4 + 32);
    float4 b0 = __ldg((const float4*)lin_b + e4);
    float4 b1 = __ldg((const float4*)lin_b + e4 + 32);

    float4* dst = out + (size_t)tok * 64;
    __stcs(dst + e4,      make_float4(a0.x + s * b0.x, a0.y + s * b0.y,
                                      a0.z + s * b0.z, a0.w + s * b0.w));
    __stcs(dst + e4 + 32, make_float4(a1.x + s * b1.x, a1.y + s * b1.y,
                                      a1.z + s * b1.z, a1.w + s * b1.w));
}

// ---------------------------------------------------------------------------
// Launch (3 kernels). Inputs: 0:x 1:custom_indices(unused) 2:v2c 3:v2r
//  4:custom_fixed_w 5:custom_train_w 6:regular_w 7:lin_w 8:lin_b
// ---------------------------------------------------------------------------
extern "C" void kernel_launch(void* const* d_in, const int* in_sizes, int n_in,
                              void* d_out, int out_size) {
    const int*   x    = (const int*)d_in[0];
    const int*   v2c  = (const int*)d_in[2];
    const int*   v2r  = (const int*)d_in[3];
    const float* fw   = (const float*)d_in[4];
    const float* tw   = (const float*)d_in[5];
    const float* Rw   = (const float*)d_in[6];
    const float* W    = (const float*)d_in[7];
    const float* bias = (const float*)d_in[8];
    float4* out = (float4*)d_out;

    int ntok = in_sizes[0];

    static bool init_done = false;
    if (!init_done) {
        cudaFuncSetAttribute(k_gemm, cudaFuncAttributeMaxDynamicSharedMemorySize,
                             SMEMF * (int)sizeof(float));
        init_done = true;
    }

    int tok_blks = (ntok + 255) / 256;
    k_prelude<<<NMB + WPREP_BLKS + tok_blks, 256>>>(fw, tw, W, x, v2c, v2r, Rw, ntok);
    k_gemm<<<NBT, 256, SMEMF * sizeof(float)>>>(bias);

    int gthreads = ntok * 32;
    k_gather<<<(gthreads + 255) / 256, 256>>>(bias, out, ntok);
}

// round 17
// speedup vs baseline: 1.2084x; 1.0043x over previous
#include <cuda_runtime.h>
#include <cstdint>

// ---------------------------------------------------------------------------
// PoincareEmbeddings: out[b,l,:] = custom ? T[cm] : Rw[rm] + lin_b
// where T[k] = lin_w @ mobius_add(logmap0(fixed[k]), train[k]) + lin_b
//
// R17 = R16 with the gather processing TWO tokens per warp: both g_tokptr
// loads issue before either row chain, doubling per-warp MLP in the measured
// latency-limited regime (R16: gather ~66us vs ~48-50us DRAM floor).
// Prelude (16.4us) and GEMM (32.7us) byte-identical to R16.
// ---------------------------------------------------------------------------

constexpr int P_    = 300;
constexpr int PPAD  = 320;
constexpr int E_    = 256;
constexpr int Kc    = 20000;
constexpr int KP1   = Kc + 1;
constexpr int KROWS = 20096;      // 314 * 64 == 1256 * 16
constexpr int NBT   = KROWS / 64; // 314 GEMM row-tiles
constexpr int NMB   = KROWS / 16; // 1256 mobius blocks
constexpr int NTOKMAX = 262144;

constexpr int WPREP_BLKS = (E_ * PPAD + 255) / 256;   // 320

__device__ float g_Mp[(size_t)KROWS * PPAD];  // fragment-permuted mobius output
__device__ float g_T[(size_t)KROWS * E_];     // projected custom embeddings (+bias)
__device__ float g_Wp[(size_t)E_ * PPAD];     // lin_w, tf32, fragment-permuted
__device__ unsigned long long g_tokptr[NTOKMAX]; // per-TOKEN row pointer | custom flag

__device__ __forceinline__ float tf32_rna(float x) {
    float r;
    asm("cvt.rna.tf32.f32 %0, %1;" : "=f"(r) : "f"(x));
    return r;
}

// ---------------------------------------------------------------------------
// Fused prelude (EXACT R16): mobius | wprep | tokptr branches by blockIdx.
// ---------------------------------------------------------------------------
constexpr int MST = 324;

__global__ void __launch_bounds__(256) k_prelude(const float* __restrict__ fixed_w,
                                                 const float* __restrict__ train_w,
                                                 const float* __restrict__ W,
                                                 const int* __restrict__ x,
                                                 const int* __restrict__ v2c,
                                                 const int* __restrict__ v2r,
                                                 const float* __restrict__ Rw,
                                                 int ntok) {
    __shared__ float stage[16 * MST];
    int bid = blockIdx.x;
    int tid = threadIdx.x;

    if (bid >= NMB) {
        int sb = bid - NMB;
        if (sb < WPREP_BLKS) {
            // ---- wprep branch ----
            int idx = sb * 256 + tid;
            if (idx < E_ * PPAD) {
                int slot = idx & 1;
                int lane = (idx >> 1) & 31;
                int t_n  = (idx >> 6) & 31;
                int t_k  = idx >> 11;
                int n = t_n * 8 + (lane >> 2);
                int k = t_k * 8 + (lane & 3) + slot * 4;
                g_Wp[idx] = (k < P_) ? tf32_rna(__ldg(W + (size_t)n * P_ + k)) : 0.f;
            }
        } else {
            // ---- tokptr branch: per-token fused row pointer ----
            int tok = (sb - WPREP_BLKS) * 256 + tid;
            if (tok < ntok) {
                int v  = __ldg(x + tok);
                int cm = __ldg(v2c + v);
                unsigned long long p;
                if (cm) {
                    p = (unsigned long long)(g_T + (size_t)cm * E_) | 1ULL;
                } else {
                    int rm = __ldg(v2r + v);
                    p = (unsigned long long)(Rw + (size_t)rm * E_);
                }
                g_tokptr[tok] = p;
            }
        }
        return;
    }

    // ---- mobius branch (verbatim R12-R16) ----
    int warp = tid >> 5;
    int lane = tid & 31;
    int mb   = bid;
    int rowBase = mb * 16;

#pragma unroll
    for (int r2 = 0; r2 < 2; r2++) {
        int row = warp * 2 + r2;
        int gr  = rowBase + row;
        int rs  = (gr < KP1) ? gr : 0;
        const float* f = fixed_w + (size_t)rs * P_;
        const float* t = train_w + (size_t)rs * P_;

        float fr[10], tr[10];
        float sf2 = 0.f, sft = 0.f, st2 = 0.f;
#pragma unroll
        for (int i = 0; i < 10; i++) {
            int p = lane + i * 32;
            float fv = (p < P_) ? __ldg(f + p) : 0.f;
            float tv = (p < P_) ? __ldg(t + p) : 0.f;
            fr[i] = fv; tr[i] = tv;
            sf2 += fv * fv;
            sft += fv * tv;
            st2 += tv * tv;
        }
#pragma unroll
        for (int off = 16; off; off >>= 1) {
            sf2 += __shfl_xor_sync(0xFFFFFFFFu, sf2, off);
            sft += __shfl_xor_sync(0xFFFFFFFFu, sft, off);
            st2 += __shfl_xor_sync(0xFFFFFFFFu, st2, off);
        }

        float norm  = sqrtf(sf2);
        float scale = (norm > 0.f) ? (atanhf(norm) / norm) : 1.0f;
        float x2 = scale * scale * sf2;
        float xy = scale * sft;
        float y2 = st2;
        float cu = 1.f + 2.f * xy + y2;
        float ct = 1.f - x2;
        float inv = 1.f / fmaxf(1.f + 2.f * xy + x2 * y2, 1e-15f);
        float alpha = cu * scale * inv;
        float beta  = ct * inv;
        if (gr >= KP1) { alpha = 0.f; beta = 0.f; }

        float* srow = stage + row * MST;
#pragma unroll
        for (int i = 0; i < 10; i++) {
            int p = lane + i * 32;
            srow[p] = tf32_rna(alpha * fr[i] + beta * tr[i]);
        }
    }
    __syncthreads();

    int t_  = mb >> 2;
    int tm  = mb & 3;
    float4* dstBase = (float4*)g_Mp;
#pragma unroll
    for (int h = 0; h < 5; h++) {
        int q   = tid + h * 256;
        int it  = q >> 7;
        int rem = q & 127;
        int kk  = rem >> 5;
        int ln  = rem & 31;
        int g   = ln >> 2;
        int tg  = ln & 3;
        int k0  = it * 32 + kk * 8 + tg;
        size_t di = ((size_t)(t_ * 10 + it) * 16 + kk * 4 + tm) * 32 + ln;
        dstBase[di] = make_float4(stage[g * MST + k0],     stage[(g + 8) * MST + k0],
                                  stage[g * MST + k0 + 4], stage[(g + 8) * MST + k0 + 4]);
    }
}

// ---------------------------------------------------------------------------
// Kernel 2: tf32 MMA GEMM with cp.async.bulk stage copies (EXACT R14-R16).
// ---------------------------------------------------------------------------
constexpr int BK    = 32;
constexpr int NIT   = PPAD / BK;      // 10
constexpr int A_ST  = 2048;           // floats
constexpr int B_ST  = 8192;           // floats
constexpr int SMEMF = 2 * (A_ST + B_ST);
constexpr unsigned STAGE_BYTES = (A_ST + B_ST) * 4;   // 40960

__device__ __forceinline__ void bulk_g2s(uint32_t dst_smem, const float* src,
                                         unsigned bytes, uint32_t mbar) {
    asm volatile(
        "cp.async.bulk.shared::cta.global.mbarrier::complete_tx::bytes "
        "[%0], [%1], %2, [%3];"
        :: "r"(dst_smem), "l"(src), "r"(bytes), "r"(mbar) : "memory");
}

__device__ __forceinline__ void mbar_wait(uint32_t mbar, unsigned parity) {
    asm volatile(
        "{\n\t"
        ".reg .pred P;\n\t"
        "WL_%=:\n\t"
        "mbarrier.try_wait.parity.acquire.cta.shared::cta.b64 P, [%0], %1, 0x989680;\n\t"
        "@P bra.uni WD_%=;\n\t"
        "bra.uni WL_%=;\n\t"
        "WD_%=:\n\t"
        "}"
        :: "r"(mbar), "r"(parity) : "memory");
}

__global__ void __launch_bounds__(256) k_gemm(const float* __restrict__ bias) {
    extern __shared__ float sm[];
    __shared__ __align__(8) unsigned long long mbar[2];

    float* Bsm[2] = { sm,            sm + B_ST };
    float* Asm[2] = { sm + 2 * B_ST, sm + 2 * B_ST + A_ST };

    int tid  = threadIdx.x;
    int warp = tid >> 5;
    int lane = tid & 31;
    int wm = warp >> 2;
    int wn = warp & 3;
    int g  = lane >> 2;
    int tg = lane & 3;
    int bt = blockIdx.x;
    int rowBase = bt * 64;

    uint32_t mb[2] = { (uint32_t)__cvta_generic_to_shared(&mbar[0]),
                       (uint32_t)__cvta_generic_to_shared(&mbar[1]) };
    if (tid == 0) {
        asm volatile("mbarrier.init.shared.b64 [%0], 1;" :: "r"(mb[0]) : "memory");
        asm volatile("mbarrier.init.shared.b64 [%0], 1;" :: "r"(mb[1]) : "memory");
    }
    __syncthreads();

    auto issue = [&](int s, int it) {   // tid 0 only
        asm volatile("mbarrier.arrive.expect_tx.shared.b64 _, [%0], %1;"
                     :: "r"(mb[s]), "r"(STAGE_BYTES) : "memory");
        bulk_g2s((uint32_t)__cvta_generic_to_shared(Bsm[s]),
                 g_Wp + (size_t)it * B_ST, B_ST * 4, mb[s]);
        bulk_g2s((uint32_t)__cvta_generic_to_shared(Asm[s]),
                 g_Mp + ((size_t)bt * NIT + it) * A_ST, A_ST * 4, mb[s]);
    };

    float acc[2][8][4];
#pragma unroll
    for (int mi = 0; mi < 2; mi++)
#pragma unroll
        for (int ni = 0; ni < 8; ni++)
#pragma unroll
            for (int r = 0; r < 4; r++) acc[mi][ni][r] = 0.f;

    if (tid == 0) issue(0, 0);

    for (int it = 0; it < NIT; it++) {
        int cur = it & 1;
        if (tid == 0 && it + 1 < NIT) issue(cur ^ 1, it + 1);

        mbar_wait(mb[cur], (unsigned)((it >> 1) & 1));

        const float* Ac = Asm[cur];
        const float* Bc = Bsm[cur];
#pragma unroll
        for (int kk = 0; kk < 4; kk++) {
            uint32_t a[2][4];
#pragma unroll
            for (int mi = 0; mi < 2; mi++) {
                float4 av = *(const float4*)(Ac + ((kk * 4 + wm * 2 + mi) * 32 + lane) * 4);
                a[mi][0] = __float_as_uint(av.x);
                a[mi][1] = __float_as_uint(av.y);
                a[mi][2] = __float_as_uint(av.z);
                a[mi][3] = __float_as_uint(av.w);
            }
#pragma unroll
            for (int ni = 0; ni < 8; ni++) {
                float2 bv = *(const float2*)(Bc + ((kk * 32 + wn * 8 + ni) * 32 + lane) * 2);
                uint32_t b0 = __float_as_uint(bv.x);
                uint32_t b1 = __float_as_uint(bv.y);
#pragma unroll
                for (int mi = 0; mi < 2; mi++) {
                    asm volatile(
                        "mma.sync.aligned.m16n8k8.row.col.f32.tf32.tf32.f32 "
                        "{%0,%1,%2,%3}, {%4,%5,%6,%7}, {%8,%9}, {%0,%1,%2,%3};"
                        : "+f"(acc[mi][ni][0]), "+f"(acc[mi][ni][1]),
                          "+f"(acc[mi][ni][2]), "+f"(acc[mi][ni][3])
                        : "r"(a[mi][0]), "r"(a[mi][1]), "r"(a[mi][2]), "r"(a[mi][3]),
                          "r"(b0), "r"(b1));
                }
            }
        }
        __syncthreads();   // close readers before next overwrite of this buffer
    }

#pragma unroll
    for (int mi = 0; mi < 2; mi++) {
#pragma unroll
        for (int ni = 0; ni < 8; ni++) {
            int col = wn * 64 + ni * 8 + tg * 2;
            float bx = __ldg(bias + col), by = __ldg(bias + col + 1);
            int r0 = rowBase + wm * 32 + mi * 16 + g;
            *(float2*)(g_T + (size_t)r0 * E_ + col) =
                make_float2(acc[mi][ni][0] + bx, acc[mi][ni][1] + by);
            *(float2*)(g_T + (size_t)(r0 + 8) * E_ + col) =
                make_float2(acc[mi][ni][2] + bx, acc[mi][ni][3] + by);
        }
    }
}

// ---------------------------------------------------------------------------
// Kernel 3: gather, TWO tokens per warp. Both tokptr loads issue before the
// row chains -> 2 independent memory chains per warp (doubled MLP).
// Per token: 2 float4/lane (identical coalescing to R16).
// ---------------------------------------------------------------------------
__global__ void __launch_bounds__(256) k_gather(const float* __restrict__ lin_b,
                                                float4* __restrict__ out,
                                                int ntok) {
    int gtid = blockIdx.x * 256 + threadIdx.x;
    int w   = gtid >> 5;          // warp id
    int e4  = gtid & 31;
    int tok0 = w * 2;
    int tok1 = tok0 + 1;
    if (tok0 >= ntok) return;
    bool has1 = (tok1 < ntok);

    // issue both pointer loads first (independent chains)
    unsigned long long t0 = __ldg(g_tokptr + tok0);
    unsigned long long t1 = has1 ? __ldg(g_tokptr + tok1) : 0;

    const float4* s0 = (const float4*)(t0 & ~1ULL);
    const float4* s1 = (const float4*)(t1 & ~1ULL);
    float f0 = (t0 & 1ULL) ? 0.f : 1.f;
    float f1 = (t1 & 1ULL) ? 0.f : 1.f;

    // issue all row loads before combining (maximize outstanding loads)
    float4 a00 = __ldg(s0 + e4);
    float4 a01 = __ldg(s0 + e4 + 32);
    float4 a10, a11;
    if (has1) { a10 = __ldg(s1 + e4); a11 = __ldg(s1 + e4 + 32); }

    float4 b0 = __ldg((const float4*)lin_b + e4);
    float4 b1 = __ldg((const float4*)lin_b + e4 + 32);

    float4* d0 = out + (size_t)tok0 * 64;
    __stcs(d0 + e4,      make_float4(a00.x + f0 * b0.x, a00.y + f0 * b0.y,
                                     a00.z + f0 * b0.z, a00.w + f0 * b0.w));
    __stcs(d0 + e4 + 32, make_float4(a01.x + f0 * b1.x, a01.y + f0 * b1.y,
                                     a01.z + f0 * b1.z, a01.w + f0 * b1.w));
    if (has1) {
        float4* d1 = out + (size_t)tok1 * 64;
        __stcs(d1 + e4,      make_float4(a10.x + f1 * b0.x, a10.y + f1 * b0.y,
                                         a10.z + f1 * b0.z, a10.w + f1 * b0.w));
        __stcs(d1 + e4 + 32, make_float4(a11.x + f1 * b1.x, a11.y + f1 * b1.y,
                                         a11.z + f1 * b1.z, a11.w + f1 * b1.w));
    }
}

// ---------------------------------------------------------------------------
// Launch (3 kernels). Inputs: 0:x 1:custom_indices(unused) 2:v2c 3:v2r
//  4:custom_fixed_w 5:custom_train_w 6:regular_w 7:lin_w 8:lin_b
// ---------------------------------------------------------------------------
extern "C" void kernel_launch(void* const* d_in, const int* in_sizes, int n_in,
                              void* d_out, int out_size) {
    const int*   x    = (const int*)d_in[0];
    const int*   v2c  = (const int*)d_in[2];
    const int*   v2r  = (const int*)d_in[3];
    const float* fw   = (const float*)d_in[4];
    const float* tw   = (const float*)d_in[5];
    const float* Rw   = (const float*)d_in[6];
    const float* W    = (const float*)d_in[7];
    const float* bias = (const float*)d_in[8];
    float4* out = (float4*)d_out;

    int ntok = in_sizes[0];

    static bool init_done = false;
    if (!init_done) {
        cudaFuncSetAttribute(k_gemm, cudaFuncAttributeMaxDynamicSharedMemorySize,
                             SMEMF * (int)sizeof(float));
        init_done = true;
    }

    int tok_blks = (ntok + 255) / 256;
    k_prelude<<<NMB + WPREP_BLKS + tok_blks, 256>>>(fw, tw, W, x, v2c, v2r, Rw, ntok);
    k_gemm<<<NBT, 256, SMEMF * sizeof(float)>>>(bias);

    // 2 tokens per warp: ntok/2 warps -> ntok*16 threads
    int gthreads = ((ntok + 1) / 2) * 32;
    k_gather<<<(gthreads + 255) / 256, 256>>>(bias, out, ntok);
}